// round 12
// baseline (speedup 1.0000x reference)
#include <cuda_runtime.h>
#include <cstdint>

#define N2    361
#define NTHR  384
#define TS    512
#define OVF   24
#define NEGV  (-1000000000.0f)
#define I32MIN_V (-2147483647 - 1)
#define GRIDB 740                     // 148 SMs * 5 resident blocks

__global__ __launch_bounds__(NTHR, 5)
void board_kernel(const float* __restrict__ logits,
                  const int* __restrict__ legal,      // bool as int32
                  const int* __restrict__ player,
                  const int* __restrict__ cur_hash,
                  const int* __restrict__ hist,
                  const int* __restrict__ move_count,
                  const int* __restrict__ ZposT,
                  const int* __restrict__ sgi,
                  const int* __restrict__ cap,
                  float* __restrict__ out,
                  int B)
{
    __shared__ int sh_tab[3][TS];     // triple-buffered exact table
    __shared__ int sh_gx[3][8];
    __shared__ int sh_ovf[3][OVF];
    __shared__ int sh_ovfn[3];
    __shared__ int sh_zd[2][N2];      // delta tables: [0]=ze^zb, [1]=ze^zw

    const int t   = threadIdx.x;
    const bool w11 = ((t >> 5) == 11);
    const int l   = t & 31;

    for (int i = t; i < N2; i += NTHR) {
        const int ze = ZposT[i];
        sh_zd[0][i] = ze ^ ZposT[N2 + i];
        sh_zd[1][i] = ze ^ ZposT[2 * N2 + i];
    }
    for (int i = t; i < 3 * TS / 4; i += NTHR)
        reinterpret_cast<int4*>(sh_tab)[i] = make_int4(-1, -1, -1, -1);
    if (t < 3) sh_ovfn[t] = 0;
    __syncthreads();

    const int g = gridDim.x;

    // prefetch for first board
    int h_cur = 0, sg_cur = 0;
    {
        const int b0 = blockIdx.x;
        if (b0 < B) {
            if (t < N2) h_cur = __ldcs(hist + b0 * N2 + t);
            if (w11)    sg_cur = __ldcs(sgi + b0 * 32 + l);
        }
    }

    // clear-state: slots this thread inserted on the PREVIOUS board
    bool pc_ins = false;
    int  pc1 = 0, pc2 = 0, pc3 = 0;
    int  P = 0, prevP = 2;            // buffer rotation

    for (int b = blockIdx.x; b < B; b += g) {
        // ---- board scalars ----
        const int pl = player[b] & 1;
        const int ch = cur_hash[b];
        int mc = move_count[b];
        if (mc < 0) mc = 0;
        if (mc > N2 - 1) mc = N2 - 1;       // mc < 361 per setup; sentinel fits

        const int idx = b * N2 + t;
        int4  c4 = make_int4(-1, -1, -1, -1);
        float lg = 0.0f;
        int   lgl = 0;
        if (t < N2) {
            c4  = __ldcs(reinterpret_cast<const int4*>(cap) + idx);
            lg  = __ldcs(logits + idx);
            lgl = __ldcs(legal + idx);
        }
        // prefetch next board's hist/sgi
        const int bn = b + g;
        int h_nxt = 0, sg_nxt = 0;
        if (bn < B) {
            if (t < N2) h_nxt = __ldcs(hist + bn * N2 + t);
            if (w11)    sg_nxt = __ldcs(sgi + bn * 32 + l);
        }

        // ---- phase 1 (pre-barrier): group XOR + CAS-only insert into buffer P ----
        if (w11) {
            int si = sg_cur;
            si = si < 0 ? 0 : (si >= N2 ? N2 - 1 : si);
            int d = sh_zd[1 - pl][si];                 // z_opp ^ z_empty
            d ^= __shfl_xor_sync(0xffffffffu, d, 1);
            d ^= __shfl_xor_sync(0xffffffffu, d, 2);
            if ((l & 3) == 0) sh_gx[P][l >> 2] = d;    // 8 groups of 4 stones
        }

        const bool ins = (t <= mc);                    // t<=mc<=360 => t<N2
        int s1 = 0, s2 = 0, s3 = 0;
        if (ins) {
            const int key = (t < mc) ? h_cur : I32MIN_V;
            const unsigned hsh = (unsigned)key * 2654435761u;
            s1 = (int)(hsh >> 23);
            s2 = (int)((hsh >> 12) & (TS - 1));
            s3 = (int)((hsh ^ (hsh >> 9)) & (TS - 1));
            int prev = atomicCAS(&sh_tab[P][s1], -1, key);
            if (prev != -1 && prev != key) {
                prev = atomicCAS(&sh_tab[P][s2], -1, key);
                if (prev != -1 && prev != key) {
                    prev = atomicCAS(&sh_tab[P][s3], -1, key);
                    if (prev != -1 && prev != key) {
                        const int oi = atomicAdd(&sh_ovfn[P], 1);
                        if (oi < OVF) sh_ovf[P][oi] = key;
                    }
                }
            }
        }
        __syncthreads();   // the ONE barrier: inserts visible, prev-board probes done

        // ---- phase 2 (post-barrier): probe buffer P + output; clear buffer prevP ----
        if (pc_ins) {      // buffer prevP is dead now; reinserted 2 boards from now
            sh_tab[prevP][pc1] = -1;
            sh_tab[prevP][pc2] = -1;
            sh_tab[prevP][pc3] = -1;
        }
        if (t == 0) sh_ovfn[prevP] = 0;

        if (t < N2) {
            int cd = 0;
            if (c4.x >= 0) cd ^= sh_gx[P][c4.x & 7];
            if (c4.y >= 0) cd ^= sh_gx[P][c4.y & 7];
            if (c4.z >= 0) cd ^= sh_gx[P][c4.z & 7];
            if (c4.w >= 0) cd ^= sh_gx[P][c4.w & 7];

            const int cand = ch ^ sh_zd[pl][t] ^ cd;

            const unsigned hh = (unsigned)cand * 2654435761u;
            bool rep = (sh_tab[P][hh >> 23] == cand) |
                       (sh_tab[P][(hh >> 12) & (TS - 1)] == cand) |
                       (sh_tab[P][(hh ^ (hh >> 9)) & (TS - 1)] == cand);

            int ovn = sh_ovfn[P];
            const bool fbk = (ovn > OVF);              // statistically unreachable
            if (ovn > OVF) ovn = OVF;
            for (int i2 = 0; i2 < ovn; ++i2) rep |= (sh_ovf[P][i2] == cand);
            if (fbk && !rep) {                          // exact global fallback
                rep = (cand == I32MIN_V);
                for (int q = 0; q < mc && !rep; ++q)
                    rep = (hist[b * N2 + q] == cand);
            }

            __stcs(out + idx, ((lgl != 0) & !rep) ? lg : NEGV);
        }

        // rotate state
        pc_ins = ins; pc1 = s1; pc2 = s2; pc3 = s3;
        prevP = P;
        P = (P == 2) ? 0 : P + 1;
        h_cur = h_nxt; sg_cur = sg_nxt;
    }
}

extern "C" void kernel_launch(void* const* d_in, const int* in_sizes, int n_in,
                              void* d_out, int out_size)
{
    const float* logits = (const float*)d_in[0];
    const int*   legal  = (const int*)d_in[1];
    const int*   player = (const int*)d_in[2];
    const int*   chash  = (const int*)d_in[3];
    const int*   hist   = (const int*)d_in[4];
    const int*   mcnt   = (const int*)d_in[5];
    const int*   zpos   = (const int*)d_in[6];
    const int*   sgi    = (const int*)d_in[7];
    const int*   cap    = (const int*)d_in[10];
    float*       out    = (float*)d_out;

    const int B = in_sizes[2];           // current_player: B elements

    board_kernel<<<GRIDB, NTHR>>>(logits, legal, player, chash, hist, mcnt,
                                  zpos, sgi, cap, out, B);
}